// round 13
// baseline (speedup 1.0000x reference)
#include <cuda_runtime.h>

#define R_BINS 64
#define Z_BINS 64
#define NBINS (R_BINS * Z_BINS)
#define NTHREADS 256
#define NBLOCKS (148 * 8)

__device__ float g_hist[NBINS];              // zeroed at load; kernel leaves it zeroed
__device__ unsigned int g_ticket;

static __device__ __forceinline__ void bin_point(float* sh, float x, float y, float z, float m) {
    const float INV_DR = 6.4f;
    const float INV_DZ = 16.0f;
    const float Z_MINf = -2.0f;
    float r2 = fmaxf(x * x + y * y, 1e-30f);
    float r = r2 * rsqrtf(r2);                 // ~2ulp sqrt: MUFU.RSQ + FMUL
    int i = (int)(r * INV_DR);                 // r >= 0 -> trunc == floor
    int j = (int)floorf((z - Z_MINf) * INV_DZ);
    if (((unsigned)i < R_BINS) & ((unsigned)j < Z_BINS)) {
        atomicAdd(sh + (i << 6) + j, m);
    }
}

__global__ void __launch_bounds__(NTHREADS, 8)
fused_hist_kernel(const float4* __restrict__ pos4,
                  const float4* __restrict__ mass4,
                  int ngroups,
                  float* __restrict__ out) {
    __shared__ float sh[NBINS];
    __shared__ int s_flag;
    for (int i = threadIdx.x; i < NBINS; i += NTHREADS) sh[i] = 0.0f;
    __syncthreads();

    const int stride = gridDim.x * NTHREADS;
    for (int g = blockIdx.x * NTHREADS + threadIdx.x; g < ngroups; g += stride) {
        // 4 points = 12 floats = 3 coalesced float4 loads + 1 float4 of masses.
        float4 a = pos4[3 * g + 0];
        float4 b = pos4[3 * g + 1];
        float4 c = pos4[3 * g + 2];
        float4 m = mass4[g];
        bin_point(sh, a.x, a.y, a.z, m.x);
        bin_point(sh, a.w, b.x, b.y, m.y);
        bin_point(sh, b.z, b.w, c.x, m.z);
        bin_point(sh, c.y, c.z, c.w, m.w);
    }

    __syncthreads();
    // Flush per-block partials to the global accumulator.
    for (int idx = threadIdx.x; idx < NBINS; idx += NTHREADS) {
        float v = sh[idx];
        if (v != 0.0f) atomicAdd(&g_hist[idx], v);
    }

    __threadfence();
    if (threadIdx.x == 0) {
        unsigned int tk = atomicAdd(&g_ticket, 1u);
        s_flag = (tk == (unsigned int)(gridDim.x - 1));
    }
    __syncthreads();

    if (s_flag) {
        __threadfence();   // all blocks' flushes visible before plain loads
        const float DRf = 0.15625f;
        const float DZf = 0.0625f;
        const float PIf = 3.14159265358979f;
        // Vectorized drain + reset (no concurrent writers after the last ticket).
        for (int q = threadIdx.x; q < NBINS / 4; q += NTHREADS) {
            float4 acc = *(float4*)&g_hist[4 * q];
            *(float4*)&g_hist[4 * q] = make_float4(0.f, 0.f, 0.f, 0.f);
            int idx = 4 * q;
            int i = idx >> 6;
            float r0 = (float)i * DRf;
            float r1 = (float)(i + 1) * DRf;
            float inv_vol = 1.0f / (PIf * (r1 * r1 - r0 * r0) * DZf);
            // 4 consecutive bins share one r-ring (4 | 64 z-bins per ring).
            out[idx + 0] = acc.x * inv_vol;
            out[idx + 1] = acc.y * inv_vol;
            out[idx + 2] = acc.z * inv_vol;
            out[idx + 3] = acc.w * inv_vol;
        }
        if (threadIdx.x == 0) atomicExch(&g_ticket, 0u);
    }
}

extern "C" void kernel_launch(void* const* d_in, const int* in_sizes, int n_in,
                              void* d_out, int out_size) {
    const float4* pos4 = (const float4*)d_in[0];   // positions [N,3] float32
    const float4* mass4 = (const float4*)d_in[1];  // masses [N] float32
    int n = in_sizes[1];
    int ngroups = n / 4;                           // N = 2^24 -> divisible

    fused_hist_kernel<<<NBLOCKS, NTHREADS>>>(pos4, mass4, ngroups, (float*)d_out);
}

// round 14
// speedup vs baseline: 1.1577x; 1.1577x over previous
#include <cuda_runtime.h>

#define R_BINS 64
#define Z_BINS 64
#define NBINS (R_BINS * Z_BINS)
#define NTHREADS 512
#define NBLOCKS (148 * 4)
// Two copies per block, selected by WARP parity: every ATOMS instruction's 32
// lanes target one copy (no wavefront split), but each copy serves only 256
// threads -> halved same-address contention. Offset by NBINS+1 so the same
// bin in the two copies lands in different banks.
#define COPY_STRIDE (NBINS + 1)

__device__ float g_hist[NBINS];              // zeroed at load; kernel leaves it zeroed
__device__ unsigned int g_ticket;

static __device__ __forceinline__ void bin_point(float* my, float x, float y, float z, float m) {
    const float INV_DR = 6.4f;
    const float INV_DZ = 16.0f;
    const float Z_MINf = -2.0f;
    float r2 = fmaxf(x * x + y * y, 1e-30f);
    float r = r2 * rsqrtf(r2);                 // ~2ulp sqrt: MUFU.RSQ + FMUL
    int i = (int)(r * INV_DR);                 // r >= 0 -> trunc == floor
    int j = (int)floorf((z - Z_MINf) * INV_DZ);
    if (((unsigned)i < R_BINS) & ((unsigned)j < Z_BINS)) {
        atomicAdd(my + (i << 6) + j, m);
    }
}

__global__ void __launch_bounds__(NTHREADS, 4)
fused_hist_kernel(const float4* __restrict__ pos4,
                  const float4* __restrict__ mass4,
                  int ngroups,
                  float* __restrict__ out) {
    __shared__ float sh[2 * COPY_STRIDE];
    __shared__ int s_flag;
    for (int i = threadIdx.x; i < 2 * COPY_STRIDE; i += NTHREADS) sh[i] = 0.0f;
    __syncthreads();

    // Warp-parity sub-histogram selection (whole warp -> one copy).
    float* my = sh + ((threadIdx.x >> 5) & 1) * COPY_STRIDE;

    const int stride = gridDim.x * NTHREADS;
    for (int g = blockIdx.x * NTHREADS + threadIdx.x; g < ngroups; g += stride) {
        // 4 points = 12 floats = 3 coalesced float4 loads + 1 float4 of masses.
        float4 a = pos4[3 * g + 0];
        float4 b = pos4[3 * g + 1];
        float4 c = pos4[3 * g + 2];
        float4 m = mass4[g];
        bin_point(my, a.x, a.y, a.z, m.x);
        bin_point(my, a.w, b.x, b.y, m.y);
        bin_point(my, b.z, b.w, c.x, m.z);
        bin_point(my, c.y, c.z, c.w, m.w);
    }

    __syncthreads();
    // Merge the two copies in smem, then flush once per block (REDs unchanged
    // vs the 4-copy baseline: 592 x 4096).
    for (int idx = threadIdx.x; idx < NBINS; idx += NTHREADS) {
        float v = sh[idx] + sh[COPY_STRIDE + idx];
        if (v != 0.0f) atomicAdd(&g_hist[idx], v);
    }

    __threadfence();
    if (threadIdx.x == 0) {
        unsigned int tk = atomicAdd(&g_ticket, 1u);
        s_flag = (tk == (unsigned int)(gridDim.x - 1));
    }
    __syncthreads();

    if (s_flag) {
        __threadfence();   // all blocks' flushes visible before plain loads
        const float DRf = 0.15625f;
        const float DZf = 0.0625f;
        const float PIf = 3.14159265358979f;
        // Vectorized drain + reset (no concurrent writers after the last ticket).
        for (int q = threadIdx.x; q < NBINS / 4; q += NTHREADS) {
            float4 acc = *(float4*)&g_hist[4 * q];
            *(float4*)&g_hist[4 * q] = make_float4(0.f, 0.f, 0.f, 0.f);
            int idx = 4 * q;
            int i = idx >> 6;
            float r0 = (float)i * DRf;
            float r1 = (float)(i + 1) * DRf;
            float inv_vol = 1.0f / (PIf * (r1 * r1 - r0 * r0) * DZf);
            // 4 consecutive bins share one r-ring (4 | 64 z-bins per ring).
            out[idx + 0] = acc.x * inv_vol;
            out[idx + 1] = acc.y * inv_vol;
            out[idx + 2] = acc.z * inv_vol;
            out[idx + 3] = acc.w * inv_vol;
        }
        if (threadIdx.x == 0) atomicExch(&g_ticket, 0u);
    }
}

extern "C" void kernel_launch(void* const* d_in, const int* in_sizes, int n_in,
                              void* d_out, int out_size) {
    const float4* pos4 = (const float4*)d_in[0];   // positions [N,3] float32
    const float4* mass4 = (const float4*)d_in[1];  // masses [N] float32
    int n = in_sizes[1];
    int ngroups = n / 4;                           // N = 2^24 -> divisible

    fused_hist_kernel<<<NBLOCKS, NTHREADS>>>(pos4, mass4, ngroups, (float*)d_out);
}